// round 16
// baseline (speedup 1.0000x reference)
#include <cuda_runtime.h>
#include <math.h>
#include <stdint.h>

#define Nn 50000
#define EE 500000
#define Hh 128
#define Ll 6
#define BM 64
#define NT 256
#define H4 32

#define SA 68    // u32 stride of packed A rows
#define SW 136   // u32 stride of packed W (k-pair rows)
#define SC 132   // float stride of C buffer

#define WHALF (64 * SW)  // 8704
#define AHALF (64 * SA)  // 4352
#define CSZ (64 * SC)

#define NB_N ((Nn + BM - 1) / BM)
#define NB_E ((EE + BM - 1) / BM)
#define NSB ((Nn + 255) / 256)  // 196 scan blocks

__device__ float g_h[(size_t)Nn * Hh];
__device__ uint32_t g_hph[(size_t)Nn * 64];  // h packed bf16 hi (k-pairs)
__device__ uint32_t g_hpl[(size_t)Nn * 64];  // h packed bf16 lo
__device__ float g_ta[(size_t)Nn * Hh];
__device__ float g_tb[(size_t)Nn * Hh];
__device__ uint32_t g_eah[(size_t)EE * 64];  // edge_attr packed bf16 hi (dst-sorted order)
__device__ uint32_t g_eal[(size_t)EE * 64];  // edge_attr packed bf16 lo (dst-sorted order)
__device__ float g_agg[(size_t)Nn * Hh];
__device__ float g_deg[Nn];
__device__ int g_cnt[Nn];    // histogram -> exclusive offsets -> ranks
__device__ int g_bsum[256];  // per-scanblock sums
__device__ int g_srcs[EE];   // src node, dst-sorted edge order
__device__ int g_dsts[EE];   // dst node, dst-sorted edge order
__device__ float g_Wc[(size_t)Ll * Hh * Hh];  // We2@Wn1agg per layer
__device__ float g_bc[Ll * Hh];               // be2@Wn1agg per layer
__device__ int g_is64;

__device__ __forceinline__ float silu_f(float v) { return v / (1.0f + expf(-v)); }

__device__ __forceinline__ int ld_idx(const void* ei, long long pos, int is64) {
    if (is64) return (int)((const long long*)ei)[pos];
    return ((const int*)ei)[pos];
}

__global__ void k_detect(const int* __restrict__ ei32) {
    int v = ei32[2 * threadIdx.x + 1];
    unsigned m = __ballot_sync(0xffffffffu, v != 0);
    if (threadIdx.x == 0) g_is64 = (m == 0u) ? 1 : 0;
}

// ---- counting sort of edges by dst (hierarchical scan) ---------------------

__global__ void k_hist(const void* __restrict__ ei) {
    long long e = (long long)blockIdx.x * 256 + threadIdx.x;
    if (e < EE) {
        int d = ld_idx(ei, (long long)EE + e, g_is64);
        atomicAdd(&g_cnt[d], 1);
    }
}

__global__ void k_deg() {
    int i = blockIdx.x * 256 + threadIdx.x;
    if (i < Nn) g_deg[i] = (float)g_cnt[i];
}

__global__ void k_scan1() {
    int i = blockIdx.x * 256 + threadIdx.x;
    int v = (i < Nn) ? g_cnt[i] : 0;
#pragma unroll
    for (int o = 16; o; o >>= 1) v += __shfl_down_sync(0xffffffffu, v, o);
    __shared__ int ws[8];
    if ((threadIdx.x & 31) == 0) ws[threadIdx.x >> 5] = v;
    __syncthreads();
    if (threadIdx.x < 8) {
        int s = ws[threadIdx.x];
#pragma unroll
        for (int o = 4; o; o >>= 1) s += __shfl_down_sync(0xffu, s, o);
        if (threadIdx.x == 0) g_bsum[blockIdx.x] = s;
    }
}

__global__ void k_scan2() {  // 1 block, 256 threads
    __shared__ int sm[256];
    int t = threadIdx.x;
    int v = (t < NSB) ? g_bsum[t] : 0;
    sm[t] = v;
    __syncthreads();
    for (int o = 1; o < 256; o <<= 1) {
        int u = (t >= o) ? sm[t - o] : 0;
        __syncthreads();
        sm[t] += u;
        __syncthreads();
    }
    if (t < NSB) g_bsum[t] = sm[t] - v;  // exclusive
}

__global__ void k_scan3() {
    int i = blockIdx.x * 256 + threadIdx.x;
    int t = threadIdx.x;
    int v = (i < Nn) ? g_cnt[i] : 0;
    __shared__ int sm[256];
    sm[t] = v;
    __syncthreads();
    for (int o = 1; o < 256; o <<= 1) {
        int u = (t >= o) ? sm[t - o] : 0;
        __syncthreads();
        sm[t] += u;
        __syncthreads();
    }
    if (i < Nn) g_cnt[i] = g_bsum[blockIdx.x] + sm[t] - v;
}

__global__ void k_scat(const void* __restrict__ ei) {
    long long e = (long long)blockIdx.x * 256 + threadIdx.x;
    if (e < EE) {
        int s = ld_idx(ei, e, g_is64);
        int d = ld_idx(ei, (long long)EE + e, g_is64);
        int pos = atomicAdd(&g_cnt[d], 1);
        g_srcs[pos] = s;
        g_dsts[pos] = d;
    }
}

// ---- weight fusion: Wc = We2@Wn1agg, bc = be2@Wn1agg (per layer) ----------

__global__ void k_fuse(const float* __restrict__ We2, const float* __restrict__ be2,
                       const float* __restrict__ Wn1) {
    extern __shared__ float fsm[];  // [0,16384): Wagg, [16384,32768): We
    float* sW = fsm;
    float* sWe = fsm + 16384;
    int l = blockIdx.x;
    const float* Wagg = Wn1 + (size_t)l * 256 * Hh + 128 * Hh;
    const float* We = We2 + (size_t)l * Hh * Hh;
    const float* be = be2 + l * Hh;
    int tid = threadIdx.x;
    for (int i = tid; i < Hh * Hh; i += 256) sW[i] = Wagg[i];
    for (int i = tid; i < Hh * Hh; i += 256) sWe[i] = We[i];
    __syncthreads();
    for (int out = tid; out < Hh * Hh; out += 256) {
        int k = out >> 7, n = out & 127;
        float s = 0.f;
#pragma unroll 8
        for (int j = 0; j < Hh; j++) s = fmaf(sWe[k * Hh + j], sW[j * Hh + n], s);
        g_Wc[(size_t)l * Hh * Hh + out] = s;
    }
    if (tid < Hh) {
        float s = 0.f;
        for (int j = 0; j < Hh; j++) s = fmaf(be[j], sW[j * Hh + tid], s);
        g_bc[l * Hh + tid] = s;
    }
}

// ---- bf16 split helpers --------------------------------------------------

__device__ __forceinline__ uint32_t pack_bf16(float lo, float hi) {
    uint32_t r;
    asm("cvt.rn.bf16x2.f32 %0, %1, %2;" : "=r"(r) : "f"(hi), "f"(lo));
    return r;
}

__device__ __forceinline__ void split2(float x, float y, uint32_t& hp, uint32_t& lp) {
    hp = pack_bf16(x, y);
    float hx = __uint_as_float(hp << 16);
    float hy = __uint_as_float(hp & 0xffff0000u);
    lp = pack_bf16(x - hx, y - hy);
}

__device__ __forceinline__ uint32_t s2u(const void* p) {
    return (uint32_t)__cvta_generic_to_shared(p);
}

// ---- W conversion --------------------------------------------------------

template <int NTHR>
__device__ __forceinline__ void conv_W(const float* __restrict__ W, uint32_t* Wh, uint32_t* Wl,
                                       int tid) {
#pragma unroll
    for (int i = 0; i < 2048 / NTHR; i++) {
        int t = tid + i * NTHR;  // 2048 tasks: 64 k2-rows x 32 n-quads
        int k2 = t >> 5, nq = t & 31;
        float4 r0 = ((const float4*)W)[(2 * k2) * 32 + nq];
        float4 r1 = ((const float4*)W)[(2 * k2 + 1) * 32 + nq];
        uint32_t* ph = Wh + k2 * SW + nq * 4;
        uint32_t* pl = Wl + k2 * SW + nq * 4;
        uint32_t h, l;
        split2(r0.x, r1.x, h, l); ph[0] = h; pl[0] = l;
        split2(r0.y, r1.y, h, l); ph[1] = h; pl[1] = l;
        split2(r0.z, r1.z, h, l); ph[2] = h; pl[2] = l;
        split2(r0.w, r1.w, h, l); ph[3] = h; pl[3] = l;
    }
}

// ---- A paths --------------------------------------------------------------

// Async copy pre-packed rows (hi/lo) into smem A tiles; zero-fills OOB.
__device__ __forceinline__ void prefetch_pk(const uint32_t* __restrict__ gh_,
                                            const uint32_t* __restrict__ gl_, long long r0,
                                            long long rmax, uint32_t* Ah, uint32_t* Al, int tid) {
#pragma unroll
    for (int i = 0; i < 8; i++) {
        int idx = tid + i * NT;
        int m = idx >> 5, q = idx & 31;
        long long r = r0 + m;
        uint32_t ssz = (r < rmax) ? 8u : 0u;
        long long rc = (r < rmax) ? r : 0;
        const void* gh = (const void*)(gh_ + rc * 64 + q * 2);
        const void* gl = (const void*)(gl_ + rc * 64 + q * 2);
        uint32_t sh = s2u(&Ah[m * SA + q * 2]);
        uint32_t sl = s2u(&Al[m * SA + q * 2]);
        asm volatile("cp.async.ca.shared.global [%0], [%1], 8, %2;" ::"r"(sh), "l"(gh), "r"(ssz));
        asm volatile("cp.async.ca.shared.global [%0], [%1], 8, %2;" ::"r"(sl), "l"(gl), "r"(ssz));
    }
    asm volatile("cp.async.commit_group;" ::: "memory");
}

// Sync copy of pre-packed rows into smem A tiles.
__device__ __forceinline__ void copy_pk(const uint32_t* __restrict__ gh_,
                                        const uint32_t* __restrict__ gl_, long long r0,
                                        long long rmax, uint32_t* Ah, uint32_t* Al, int tid) {
#pragma unroll
    for (int i = 0; i < 8; i++) {
        int idx = tid + i * NT;
        int m = idx >> 5, q = idx & 31;
        uint2 h = make_uint2(0u, 0u), l = make_uint2(0u, 0u);
        if (r0 + m < rmax) {
            h = ((const uint2*)(gh_ + (r0 + m) * 64))[q];
            l = ((const uint2*)(gl_ + (r0 + m) * 64))[q];
        }
        *(uint2*)&Ah[m * SA + q * 2] = h;
        *(uint2*)&Al[m * SA + q * 2] = l;
    }
}

__device__ __forceinline__ void conv_A_scaled(const float* __restrict__ g, long long r0,
                                              long long rmax, uint32_t* Ah, uint32_t* Al, int tid,
                                              const float* __restrict__ rden) {
#pragma unroll
    for (int i = 0; i < 8; i++) {
        int idx = tid + i * NT;
        int m = idx >> 5, q = idx & 31;
        float4 v = make_float4(0.f, 0.f, 0.f, 0.f);
        if (r0 + m < rmax) {
            v = ((const float4*)g)[(r0 + m) * (long long)H4 + q];
            float s = rden[m];
            v.x *= s; v.y *= s; v.z *= s; v.w *= s;
        }
        uint32_t h, l;
        split2(v.x, v.y, h, l);
        Ah[m * SA + q * 2] = h; Al[m * SA + q * 2] = l;
        split2(v.z, v.w, h, l);
        Ah[m * SA + q * 2 + 1] = h; Al[m * SA + q * 2 + 1] = l;
    }
}

// ---- mma ------------------------------------------------------------------

__device__ __forceinline__ void mma_b(float c[4], uint32_t a0, uint32_t a1, uint32_t a2,
                                      uint32_t a3, uint32_t b0, uint32_t b1) {
    asm volatile(
        "mma.sync.aligned.m16n8k16.row.col.f32.bf16.bf16.f32 "
        "{%0,%1,%2,%3},{%4,%5,%6,%7},{%8,%9},{%0,%1,%2,%3};"
        : "+f"(c[0]), "+f"(c[1]), "+f"(c[2]), "+f"(c[3])
        : "r"(a0), "r"(a1), "r"(a2), "r"(a3), "r"(b0), "r"(b1));
}

__device__ __forceinline__ void zero_acc(float acc[2][4][4]) {
#pragma unroll
    for (int mt = 0; mt < 2; mt++)
#pragma unroll
        for (int nt = 0; nt < 4; nt++)
#pragma unroll
            for (int j = 0; j < 4; j++) acc[mt][nt][j] = 0.f;
}

// warp tile 32x32 at (wm*32, wn*32); 3-term bf16 split.
__device__ __forceinline__ void mma_gemm(const uint32_t* __restrict__ Ah,
                                         const uint32_t* __restrict__ Al,
                                         const uint32_t* __restrict__ Wh,
                                         const uint32_t* __restrict__ Wl, float acc[2][4][4],
                                         int lane, int wm, int wn) {
    int g = lane >> 2, tg = lane & 3;
#pragma unroll 1
    for (int kc = 0; kc < 8; kc++) {
        uint32_t ah[2][4], al[2][4], bh[4][2], bl[4][2];
#pragma unroll
        for (int mt = 0; mt < 2; mt++) {
            const uint32_t* p = Ah + (wm * 32 + mt * 16 + g) * SA + kc * 8;
            const uint32_t* q = Al + (wm * 32 + mt * 16 + g) * SA + kc * 8;
            ah[mt][0] = p[tg]; ah[mt][1] = p[8 * SA + tg];
            ah[mt][2] = p[tg + 4]; ah[mt][3] = p[8 * SA + tg + 4];
            al[mt][0] = q[tg]; al[mt][1] = q[8 * SA + tg];
            al[mt][2] = q[tg + 4]; al[mt][3] = q[8 * SA + tg + 4];
        }
#pragma unroll
        for (int nt = 0; nt < 4; nt++) {
            const uint32_t* p = Wh + (kc * 8 + tg) * SW + wn * 32 + nt * 8 + g;
            const uint32_t* q = Wl + (kc * 8 + tg) * SW + wn * 32 + nt * 8 + g;
            bh[nt][0] = p[0]; bh[nt][1] = p[4 * SW];
            bl[nt][0] = q[0]; bl[nt][1] = q[4 * SW];
        }
#pragma unroll
        for (int mt = 0; mt < 2; mt++)
#pragma unroll
            for (int nt = 0; nt < 4; nt++) {
                mma_b(acc[mt][nt], ah[mt][0], ah[mt][1], ah[mt][2], ah[mt][3], bh[nt][0], bh[nt][1]);
                mma_b(acc[mt][nt], ah[mt][0], ah[mt][1], ah[mt][2], ah[mt][3], bl[nt][0], bl[nt][1]);
                mma_b(acc[mt][nt], al[mt][0], al[mt][1], al[mt][2], al[mt][3], bh[nt][0], bh[nt][1]);
            }
    }
}

__device__ __forceinline__ void store_C(const float acc[2][4][4], float* C, int lane, int wm,
                                        int wn) {
    int g = lane >> 2, tg = lane & 3;
#pragma unroll
    for (int mt = 0; mt < 2; mt++)
#pragma unroll
        for (int nt = 0; nt < 4; nt++) {
            int r = wm * 32 + mt * 16 + g;
            int c = wn * 32 + nt * 8 + 2 * tg;
            *(float2*)(C + r * SC + c) = make_float2(acc[mt][nt][0], acc[mt][nt][1]);
            *(float2*)(C + (r + 8) * SC + c) = make_float2(acc[mt][nt][2], acc[mt][nt][3]);
        }
}

__device__ __forceinline__ void out_direct(const float acc[2][4][4], float* __restrict__ out,
                                           long long r0, long long rmax, int lane, int wm, int wn,
                                           const float* bias) {
    int g = lane >> 2, tg = lane & 3;
#pragma unroll
    for (int mt = 0; mt < 2; mt++)
#pragma unroll
        for (int nt = 0; nt < 4; nt++) {
            int r = wm * 32 + mt * 16 + g;
            int c = wn * 32 + nt * 8 + 2 * tg;
            float bx = 0.f, by = 0.f;
            if (bias) { bx = bias[c]; by = bias[c + 1]; }
            if (r0 + r < rmax)
                *(float2*)(out + (r0 + r) * (long long)Hh + c) =
                    make_float2(acc[mt][nt][0] + bx, acc[mt][nt][1] + by);
            if (r0 + r + 8 < rmax)
                *(float2*)(out + (r0 + r + 8) * (long long)Hh + c) =
                    make_float2(acc[mt][nt][2] + bx, acc[mt][nt][3] + by);
        }
}

// ---- node encoder (2 CTAs/SM) ---------------------------------------------
// Writes fp32 g_h AND packed g_hph/g_hpl.

__global__ __launch_bounds__(NT, 2) void k_node_encode(const float* __restrict__ x,
                                                       const float* __restrict__ W1,
                                                       const float* __restrict__ b1,
                                                       const float* __restrict__ W2,
                                                       const float* __restrict__ b2) {
    extern __shared__ __align__(16) uint32_t dsm[];
    uint32_t* Wh = dsm;
    uint32_t* Wl = Wh + WHALF;
    uint32_t* Ah = Wl + WHALF;
    uint32_t* Al = Ah + AHALF;
    __shared__ float xt[BM][3];
    __shared__ __align__(16) float W1s[3 * Hh];
    __shared__ __align__(16) float b1s[Hh];
    __shared__ __align__(16) float b2s[Hh];
    int tid = threadIdx.x, lane = tid & 31, w = tid >> 5, wm = w & 1, wn = w >> 1;
    int tx = tid & 31, ty = tid >> 5;
    int gq = lane >> 2, tgq = lane & 3;
    long long r0 = (long long)blockIdx.x * BM;

    if (tid < BM) {
        long long m = r0 + tid;
        float a = 0.f, bb = 0.f, c = 0.f;
        if (m < Nn) { a = x[m * 3 + 0]; bb = x[m * 3 + 1]; c = x[m * 3 + 2]; }
        xt[tid][0] = a; xt[tid][1] = bb; xt[tid][2] = c;
    }
    if (tid < Hh) { b1s[tid] = b1[tid]; b2s[tid] = b2[tid]; }
    for (int i = tid; i < 3 * Hh; i += NT) W1s[i] = W1[i];
    conv_W<NT>(W2, Wh, Wl, tid);
    __syncthreads();

    int row0 = ty * 8, col0 = tx * 4;
#pragma unroll
    for (int i = 0; i < 8; i++) {
        int r = row0 + i;
        float v[4];
#pragma unroll
        for (int j = 0; j < 4; j++) {
            int c = col0 + j;
            v[j] = silu_f(b1s[c] + xt[r][0] * W1s[c] + xt[r][1] * W1s[Hh + c] +
                          xt[r][2] * W1s[2 * Hh + c]);
        }
        uint32_t h, l;
        split2(v[0], v[1], h, l);
        Ah[r * SA + tx * 2] = h; Al[r * SA + tx * 2] = l;
        split2(v[2], v[3], h, l);
        Ah[r * SA + tx * 2 + 1] = h; Al[r * SA + tx * 2 + 1] = l;
    }
    __syncthreads();

    float acc[2][4][4];
    zero_acc(acc);
    mma_gemm(Ah, Al, Wh, Wl, acc, lane, wm, wn);

#pragma unroll
    for (int mt = 0; mt < 2; mt++)
#pragma unroll
        for (int nt = 0; nt < 4; nt++) {
            int r = wm * 32 + mt * 16 + gq;
            int c = wn * 32 + nt * 8 + 2 * tgq;
            int k2 = c >> 1;
            float bx = b2s[c], by = b2s[c + 1];
            uint32_t h, l;
            if (r0 + r < Nn) {
                float v0 = acc[mt][nt][0] + bx, v1 = acc[mt][nt][1] + by;
                *(float2*)(g_h + (r0 + r) * (long long)Hh + c) = make_float2(v0, v1);
                split2(v0, v1, h, l);
                g_hph[(r0 + r) * 64 + k2] = h;
                g_hpl[(r0 + r) * 64 + k2] = l;
            }
            if (r0 + r + 8 < Nn) {
                float v0 = acc[mt][nt][2] + bx, v1 = acc[mt][nt][3] + by;
                *(float2*)(g_h + (r0 + r + 8) * (long long)Hh + c) = make_float2(v0, v1);
                split2(v0, v1, h, l);
                g_hph[(r0 + r + 8) * 64 + k2] = h;
                g_hpl[(r0 + r + 8) * 64 + k2] = l;
            }
        }
}

// ---- edge encoder (persistent, dst-sorted order, 2 CTAs/SM) ----------------

__global__ __launch_bounds__(NT, 2) void k_edge_encode(const float* __restrict__ coords,
                                                       const float* __restrict__ W1,
                                                       const float* __restrict__ b1,
                                                       const float* __restrict__ W2,
                                                       const float* __restrict__ b2) {
    extern __shared__ __align__(16) uint32_t dsm[];
    uint32_t* Wh = dsm;
    uint32_t* Wl = Wh + WHALF;
    uint32_t* Ah = Wl + WHALF;
    uint32_t* Al = Ah + AHALF;
    __shared__ float ef[BM][4];
    __shared__ __align__(16) float W1s[4 * Hh];
    __shared__ __align__(16) float b1s[Hh];
    __shared__ __align__(16) float b2s[Hh];
    int tid = threadIdx.x, lane = tid & 31, w = tid >> 5, wm = w & 1, wn = w >> 1;
    int tx = tid & 31, ty = tid >> 5;
    int g = lane >> 2, tg = lane & 3;

    if (tid < Hh) { b1s[tid] = b1[tid]; b2s[tid] = b2[tid]; }
    for (int i = tid; i < 4 * Hh; i += NT) W1s[i] = W1[i];
    conv_W<NT>(W2, Wh, Wl, tid);
    __syncthreads();

    for (long long tile = blockIdx.x; tile < NB_E; tile += gridDim.x) {
        long long e0 = tile * BM;
        if (tid < BM) {
            long long e = e0 + tid;
            float dx = 0.f, dy = 0.f, dz = 0.f, nr = 0.f;
            if (e < EE) {
                int s = g_srcs[e];
                int d = g_dsts[e];
                dx = coords[(size_t)d * 3 + 0] - coords[(size_t)s * 3 + 0];
                dy = coords[(size_t)d * 3 + 1] - coords[(size_t)s * 3 + 1];
                dz = coords[(size_t)d * 3 + 2] - coords[(size_t)s * 3 + 2];
                nr = sqrtf(dx * dx + dy * dy + dz * dz);
            }
            ef[tid][0] = dx; ef[tid][1] = dy; ef[tid][2] = dz; ef[tid][3] = nr;
        }
        __syncthreads();

        int row0 = ty * 8, col0 = tx * 4;
#pragma unroll
        for (int i = 0; i < 8; i++) {
            int r = row0 + i;
            float v[4];
#pragma unroll
            for (int j = 0; j < 4; j++) {
                int c = col0 + j;
                v[j] = silu_f(b1s[c] + ef[r][0] * W1s[c] + ef[r][1] * W1s[Hh + c] +
                              ef[r][2] * W1s[2 * Hh + c] + ef[r][3] * W1s[3 * Hh + c]);
            }
            uint32_t h, l;
            split2(v[0], v[1], h, l);
            Ah[r * SA + tx * 2] = h; Al[r * SA + tx * 2] = l;
            split2(v[2], v[3], h, l);
            Ah[r * SA + tx * 2 + 1] = h; Al[r * SA + tx * 2 + 1] = l;
        }
        __syncthreads();

        float acc[2][4][4];
        zero_acc(acc);
        mma_gemm(Ah, Al, Wh, Wl, acc, lane, wm, wn);

        // packed epilogue: split (acc + b2) into hi/lo and store (sorted position)
#pragma unroll
        for (int mt = 0; mt < 2; mt++)
#pragma unroll
            for (int nt = 0; nt < 4; nt++) {
                int r = wm * 32 + mt * 16 + g;
                int c = wn * 32 + nt * 8 + 2 * tg;
                int k2 = c >> 1;
                float bx = b2s[c], by = b2s[c + 1];
                uint32_t h, l;
                if (e0 + r < EE) {
                    split2(acc[mt][nt][0] + bx, acc[mt][nt][1] + by, h, l);
                    g_eah[(e0 + r) * 64 + k2] = h;
                    g_eal[(e0 + r) * 64 + k2] = l;
                }
                if (e0 + r + 8 < EE) {
                    split2(acc[mt][nt][2] + bx, acc[mt][nt][3] + by, h, l);
                    g_eah[(e0 + r + 8) * 64 + k2] = h;
                    g_eal[(e0 + r + 8) * 64 + k2] = l;
                }
            }
        __syncthreads();
    }
}

// ---- per layer: ta/tb (persistent, parity-split, cp.async pipelined) -------

__global__ __launch_bounds__(NT, 2) void k_tatb(const float* __restrict__ W1) {
    extern __shared__ __align__(16) uint32_t dsm[];
    uint32_t* Wh = dsm;
    uint32_t* Wl = Wh + WHALF;
    uint32_t* Ah = Wl + WHALF;
    uint32_t* Al = Ah + AHALF;
    int tid = threadIdx.x, lane = tid & 31, w = tid >> 5, wm = w & 1, wn = w >> 1;
    int part = blockIdx.x & 1;  // 0 -> W1a/g_ta, 1 -> W1b/g_tb

    conv_W<NT>(W1 + part * Hh * Hh, Wh, Wl, tid);
    float* outp = part ? g_tb : g_ta;

    long long tile = blockIdx.x >> 1;
    long long step = gridDim.x >> 1;
    if (tile < NB_N) prefetch_pk(g_hph, g_hpl, tile * BM, Nn, Ah, Al, tid);

    for (; tile < NB_N; tile += step) {
        asm volatile("cp.async.wait_group 0;" ::: "memory");
        __syncthreads();  // A ready + conv_W complete

        float acc[2][4][4];
        zero_acc(acc);
        mma_gemm(Ah, Al, Wh, Wl, acc, lane, wm, wn);
        __syncthreads();  // all A reads done; safe to overwrite

        long long next = tile + step;
        if (next < NB_N) prefetch_pk(g_hph, g_hpl, next * BM, Nn, Ah, Al, tid);
        out_direct(acc, outp, tile * BM, Nn, lane, wm, wn, 0);
    }
}

// ---- per layer: fused edge kernel (persistent, dst-sorted, cp.async) ------
// hid = silu(ea@W1c + b1 + ta[dst] + tb[src]); scatter hid to g_agg[dst].

__global__ __launch_bounds__(NT, 2) void k_edge(const float* __restrict__ W1,
                                                const float* __restrict__ b1) {
    extern __shared__ __align__(16) uint32_t dsm[];
    uint32_t* W1h = dsm;
    uint32_t* W1l = W1h + WHALF;
    uint32_t* Ah = W1l + WHALF;
    uint32_t* Al = Ah + AHALF;
    __shared__ int dsts[2][BM];
    __shared__ int srcs[2][BM];
    __shared__ __align__(16) float b1s[Hh];
    int tid = threadIdx.x, lane = tid & 31, w = tid >> 5, wm = w & 1, wn = w >> 1;
    int g = lane >> 2, tg = lane & 3;

    if (tid < Hh) b1s[tid] = b1[tid];
    conv_W<NT>(W1 + 256 * Hh, W1h, W1l, tid);  // W1c rows [256,384)

    long long tile = blockIdx.x;
    int buf = 0;
    prefetch_pk(g_eah, g_eal, tile * BM, EE, Ah, Al, tid);
    if (tid < BM) {
        long long e = tile * BM + tid;
        int s = 0, d = 0;
        if (e < EE) { s = g_srcs[e]; d = g_dsts[e]; }
        srcs[0][tid] = s;
        dsts[0][tid] = d;
    }

    for (; tile < NB_E; tile += gridDim.x) {
        long long e0 = tile * BM;
        asm volatile("cp.async.wait_group 0;" ::: "memory");
        __syncthreads();  // A + idx[buf] + W ready

        float acc[2][4][4];
        zero_acc(acc);
        mma_gemm(Ah, Al, W1h, W1l, acc, lane, wm, wn);
        __syncthreads();  // all A reads done; safe to overwrite

        long long next = tile + gridDim.x;
        if (next < NB_E) {
            prefetch_pk(g_eah, g_eal, next * BM, EE, Ah, Al, tid);  // overlaps epilogue
            if (tid < BM) {
                long long e = next * BM + tid;
                int s = 0, d = 0;
                if (e < EE) { s = g_srcs[e]; d = g_dsts[e]; }
                srcs[1 - buf][tid] = s;
                dsts[1 - buf][tid] = d;
            }
        }

        // epilogue: silu + gather ta/tb, scatter hid straight to g_agg[dst]
#pragma unroll
        for (int mt = 0; mt < 2; mt++)
#pragma unroll
            for (int half = 0; half < 2; half++) {
                int r = wm * 32 + mt * 16 + g + half * 8;
                long long e = e0 + r;
                if (e < EE) {
                    int dd = dsts[buf][r], ss = srcs[buf][r];
                    const float* tap = g_ta + (size_t)dd * Hh;
                    const float* tbp = g_tb + (size_t)ss * Hh;
                    float* aggp = g_agg + (size_t)dd * Hh;
#pragma unroll
                    for (int nt = 0; nt < 4; nt++) {
                        int c = wn * 32 + nt * 8 + 2 * tg;
                        float2 tav = *(const float2*)(tap + c);
                        float2 tbv = *(const float2*)(tbp + c);
                        float v0 = silu_f(acc[mt][nt][half * 2 + 0] + b1s[c] + tav.x + tbv.x);
                        float v1 = silu_f(acc[mt][nt][half * 2 + 1] + b1s[c + 1] + tav.y + tbv.y);
                        asm volatile("red.global.add.v2.f32 [%0], {%1,%2};" ::"l"(aggp + c),
                                     "f"(v0), "f"(v1)
                                     : "memory");
                    }
                }
            }
        buf ^= 1;
    }
}

// ---- per layer: node update (3 GEMMs, no C buffer, 2 CTAs/SM) --------------
// Writes fp32 g_h AND packed g_hph/g_hpl.

__global__ __launch_bounds__(NT, 2) void k_node_update(const float* __restrict__ Wc,
                                                       const float* __restrict__ bc,
                                                       const float* __restrict__ Wn1,
                                                       const float* __restrict__ bn1,
                                                       const float* __restrict__ Wn2,
                                                       const float* __restrict__ bn2,
                                                       const float* __restrict__ lg,
                                                       const float* __restrict__ lb) {
    extern __shared__ __align__(16) uint32_t dsm[];
    uint32_t* Wh = dsm;
    uint32_t* Wl = Wh + WHALF;
    uint32_t* Ah = Wl + WHALF;
    uint32_t* Al = Ah + AHALF;
    __shared__ float rden[BM];
    __shared__ float cdeg[BM];
    __shared__ __align__(16) float bcs[Hh];   // bc
    __shared__ __align__(16) float b1s[Hh];   // bn1
    __shared__ __align__(16) float b2s[Hh];   // bn2
    __shared__ __align__(16) float gs[Hh];
    __shared__ __align__(16) float bs[Hh];
    __shared__ float red_s[BM][4];
    __shared__ float red_q[BM][4];
    int tid = threadIdx.x, lane = tid & 31, w = tid >> 5, wm = w & 1, wn = w >> 1;
    int g = lane >> 2, tg = lane & 3;
    long long r0 = (long long)blockIdx.x * BM;

    if (tid < BM) {
        long long m = r0 + tid;
        float dg = (m < Nn) ? g_deg[m] : 0.f;
        rden[tid] = 1.0f / fmaxf(dg, 1.0f);
        cdeg[tid] = (dg > 0.f) ? 1.f : 0.f;
    }
    if (tid < Hh) {
        bcs[tid] = bc[tid];
        b1s[tid] = bn1[tid];
        b2s[tid] = bn2[tid];
        gs[tid] = lg[tid];
        bs[tid] = lb[tid];
    }
    __syncthreads();  // rden/cdeg visible before conv_A_scaled

    // 1) u = agg/denom ; Wc
    conv_A_scaled(g_agg, r0, Nn, Ah, Al, tid, rden);
    conv_W<NT>(Wc, Wh, Wl, tid);
    __syncthreads();

    // 2) acc = u@Wc
    float acc[2][4][4];
    zero_acc(acc);
    mma_gemm(Ah, Al, Wh, Wl, acc, lane, wm, wn);
    __syncthreads();

    // 3) h part: acc += h@Wn1h (packed h copy, no conversion)
    copy_pk(g_hph, g_hpl, r0, Nn, Ah, Al, tid);
    conv_W<NT>(Wn1, Wh, Wl, tid);  // Wn1 h part (rows [0,128))
    __syncthreads();
    mma_gemm(Ah, Al, Wh, Wl, acc, lane, wm, wn);
    __syncthreads();  // all reads of Ah/Al + Wh/Wl done before overwrite

    // 4) silu(acc + bn1 + cdeg*bc) -> packed A (acc layout) ; Wn2
#pragma unroll
    for (int mt = 0; mt < 2; mt++)
#pragma unroll
        for (int half = 0; half < 2; half++) {
            int r = wm * 32 + mt * 16 + g + half * 8;
            float cf = cdeg[r];
#pragma unroll
            for (int nt = 0; nt < 4; nt++) {
                int c = wn * 32 + nt * 8 + 2 * tg;
                float v0 = silu_f(acc[mt][nt][half * 2 + 0] + b1s[c] + cf * bcs[c]);
                float v1 = silu_f(acc[mt][nt][half * 2 + 1] + b1s[c + 1] + cf * bcs[c + 1]);
                uint32_t h, l;
                split2(v0, v1, h, l);
                int k2 = wn * 16 + nt * 4 + tg;
                Ah[r * SA + k2] = h;
                Al[r * SA + k2] = l;
            }
        }
    conv_W<NT>(Wn2, Wh, Wl, tid);
    __syncthreads();

    // 5) acc = hidden@Wn2
    zero_acc(acc);
    mma_gemm(Ah, Al, Wh, Wl, acc, lane, wm, wn);

    // 6) residual + layernorm, all in acc layout
#pragma unroll
    for (int mt = 0; mt < 2; mt++)
#pragma unroll
        for (int half = 0; half < 2; half++) {
            int r = wm * 32 + mt * 16 + g + half * 8;
            long long m = r0 + r;
            float s = 0.f, q = 0.f;
#pragma unroll
            for (int nt = 0; nt < 4; nt++) {
                int c = wn * 32 + nt * 8 + 2 * tg;
                float2 hv = make_float2(0.f, 0.f);
                if (m < Nn) hv = *(const float2*)(g_h + m * (long long)Hh + c);
                float v0 = acc[mt][nt][half * 2 + 0] + b2s[c] + hv.x;
                float v1 = acc[mt][nt][half * 2 + 1] + b2s[c + 1] + hv.y;
                acc[mt][nt][half * 2 + 0] = v0;
                acc[mt][nt][half * 2 + 1] = v1;
                s += v0 + v1;
                q += v0 * v0 + v1 * v1;
            }
            s += __shfl_xor_sync(0xffffffffu, s, 1);
            q += __shfl_xor_sync(0xffffffffu, q, 1);
            s += __shfl_xor_sync(0xffffffffu, s, 2);
            q += __shfl_xor_sync(0xffffffffu, q, 2);
            if (tg == 0) { red_s[r][wn] = s; red_q[r][wn] = q; }
        }
    __syncthreads();

#pragma unroll
    for (int mt = 0; mt < 2; mt++)
#pragma unroll
        for (int half = 0; half < 2; half++) {
            int r = wm * 32 + mt * 16 + g + half * 8;
            long long m = r0 + r;
            float s = red_s[r][0] + red_s[r][1] + red_s[r][2] + red_s[r][3];
            float q = red_q[r][0] + red_q[r][1] + red_q[r][2] + red_q[r][3];
            float mean = s * (1.0f / Hh);
            float var = q * (1.0f / Hh) - mean * mean;
            float inv = 1.0f / sqrtf(var + 1e-5f);
            if (m < Nn) {
#pragma unroll
                for (int nt = 0; nt < 4; nt++) {
                    int c = wn * 32 + nt * 8 + 2 * tg;
                    float o0 = (acc[mt][nt][half * 2 + 0] - mean) * inv * gs[c] + bs[c];
                    float o1 = (acc[mt][nt][half * 2 + 1] - mean) * inv * gs[c + 1] + bs[c + 1];
                    *(float2*)(g_h + m * (long long)Hh + c) = make_float2(o0, o1);
                    uint32_t h, l;
                    split2(o0, o1, h, l);
                    int k2 = c >> 1;
                    g_hph[m * 64 + k2] = h;
                    g_hpl[m * 64 + k2] = l;
                }
            }
        }
}

// ---- decoder --------------------------------------------------------------

__global__ __launch_bounds__(NT, 1) void k_decode(const float* __restrict__ W1,
                                                  const float* __restrict__ b1,
                                                  const float* __restrict__ W2,
                                                  const float* __restrict__ b2,
                                                  float* __restrict__ out) {
    extern __shared__ __align__(16) uint32_t dsm[];
    uint32_t* Wh = dsm;
    uint32_t* Wl = Wh + WHALF;
    uint32_t* Ah = Wl + WHALF;
    uint32_t* Al = Ah + AHALF;
    float* C = (float*)(Al + AHALF);
    __shared__ __align__(16) float b1s[Hh];
    __shared__ float W2s[Hh * 9];
    __shared__ float b2s[9];
    int tid = threadIdx.x, lane = tid & 31, w = tid >> 5, wm = w & 1, wn = w >> 1;
    int tx = tid & 31, ty = tid >> 5;
    int row0 = ty * 8, col0 = tx * 4;
    long long r0 = (long long)blockIdx.x * BM;

    if (tid < Hh) b1s[tid] = b1[tid];
    if (tid < 9) b2s[tid] = b2[tid];
    for (int i = tid; i < Hh * 9; i += NT) W2s[i] = W2[i];
    copy_pk(g_hph, g_hpl, r0, Nn, Ah, Al, tid);
    conv_W<NT>(W1, Wh, Wl, tid);
    __syncthreads();

    float acc[2][4][4];
    zero_acc(acc);
    mma_gemm(Ah, Al, Wh, Wl, acc, lane, wm, wn);
    __syncthreads();
    store_C(acc, C, lane, wm, wn);
    __syncthreads();

#pragma unroll
    for (int i = 0; i < 8; i++) {
        int r = row0 + i;
        float4 cv = *(const float4*)(C + r * SC + col0);
        cv.x = silu_f(cv.x + b1s[col0 + 0]);
        cv.y = silu_f(cv.y + b1s[col0 + 1]);
        cv.z = silu_f(cv.z + b1s[col0 + 2]);
        cv.w = silu_f(cv.w + b1s[col0 + 3]);
        *(float4*)(C + r * SC + col0) = cv;
    }
    __syncthreads();

    for (int idx = tid; idx < BM * 9; idx += NT) {
        int r = idx / 9;
        int c = idx % 9;
        long long m = r0 + r;
        if (m < Nn) {
            float sum = 0.f;
            const float* hrow = C + r * SC;
#pragma unroll 4
            for (int k = 0; k < Hh; k++) sum = fmaf(hrow[k], W2s[k * 9 + c], sum);
            out[m * 9 + c] = sum + b2s[c];
        }
    }
}

// ---- host -----------------------------------------------------------------

extern "C" void kernel_launch(void* const* d_in, const int* in_sizes, int n_in, void* d_out,
                              int out_size) {
    const float* x = (const float*)d_in[0];
    const float* coords = (const float*)d_in[1];
    const void* ei = d_in[2];
    const float* Wne1 = (const float*)d_in[3];
    const float* bne1 = (const float*)d_in[4];
    const float* Wne2 = (const float*)d_in[5];
    const float* bne2 = (const float*)d_in[6];
    const float* Wee1 = (const float*)d_in[7];
    const float* bee1 = (const float*)d_in[8];
    const float* Wee2 = (const float*)d_in[9];
    const float* bee2 = (const float*)d_in[10];
    const float* We1 = (const float*)d_in[11];
    const float* be1 = (const float*)d_in[12];
    const float* We2 = (const float*)d_in[13];
    const float* be2 = (const float*)d_in[14];
    const float* Wn1 = (const float*)d_in[15];
    const float* bn1 = (const float*)d_in[16];
    const float* Wn2 = (const float*)d_in[17];
    const float* bn2 = (const float*)d_in[18];
    const float* lng = (const float*)d_in[19];
    const float* lnb = (const float*)d_in[20];
    const float* Wd1 = (const float*)d_in[21];
    const float* bd1 = (const float*)d_in[22];
    const float* Wd2 = (const float*)d_in[23];
    const float* bd2 = (const float*)d_in[24];
    float* out = (float*)d_out;

    const int SM_SMALL = (2 * WHALF + 2 * AHALF) * 4;        // 104448 (2 CTAs/SM)
    const int SM_C = (2 * WHALF + 2 * AHALF) * 4 + CSZ * 4;  // 138240 (decode)
    const int SM_FUSE = 131072;

    cudaFuncSetAttribute(k_node_encode, cudaFuncAttributeMaxDynamicSharedMemorySize, SM_SMALL);
    cudaFuncSetAttribute(k_edge_encode, cudaFuncAttributeMaxDynamicSharedMemorySize, SM_SMALL);
    cudaFuncSetAttribute(k_tatb, cudaFuncAttributeMaxDynamicSharedMemorySize, SM_SMALL);
    cudaFuncSetAttribute(k_edge, cudaFuncAttributeMaxDynamicSharedMemorySize, SM_SMALL);
    cudaFuncSetAttribute(k_node_update, cudaFuncAttributeMaxDynamicSharedMemorySize, SM_SMALL);
    cudaFuncSetAttribute(k_decode, cudaFuncAttributeMaxDynamicSharedMemorySize, SM_C);
    cudaFuncSetAttribute(k_fuse, cudaFuncAttributeMaxDynamicSharedMemorySize, SM_FUSE);

    int dev = 0, sms = 148;
    cudaGetDevice(&dev);
    cudaDeviceGetAttribute(&sms, cudaDevAttrMultiProcessorCount, dev);

    void* p_agg = 0;
    void* p_cnt = 0;
    cudaGetSymbolAddress(&p_agg, g_agg);
    cudaGetSymbolAddress(&p_cnt, g_cnt);

    void* p_Wc = 0;
    void* p_bc = 0;
    cudaGetSymbolAddress(&p_Wc, g_Wc);
    cudaGetSymbolAddress(&p_bc, g_bc);
    const float* Wc = (const float*)p_Wc;
    const float* bcp = (const float*)p_bc;

    k_detect<<<1, 32>>>((const int*)ei);
    cudaMemsetAsync(p_cnt, 0, Nn * sizeof(int));
    k_hist<<<(EE + 255) / 256, 256>>>(ei);
    k_deg<<<NSB, 256>>>();
    k_scan1<<<NSB, 256>>>();
    k_scan2<<<1, 256>>>();
    k_scan3<<<NSB, 256>>>();
    k_scat<<<(EE + 255) / 256, 256>>>(ei);
    k_fuse<<<Ll, 256, SM_FUSE>>>(We2, be2, Wn1);
    k_node_encode<<<NB_N, NT, SM_SMALL>>>(x, Wne1, bne1, Wne2, bne2);
    k_edge_encode<<<2 * sms, NT, SM_SMALL>>>(coords, Wee1, bee1, Wee2, bee2);

    for (int l = 0; l < Ll; l++) {
        cudaMemsetAsync(p_agg, 0, (size_t)Nn * Hh * sizeof(float));
        k_tatb<<<2 * sms, NT, SM_SMALL>>>(We1 + (size_t)l * 384 * Hh);
        k_edge<<<2 * sms, NT, SM_SMALL>>>(We1 + (size_t)l * 384 * Hh, be1 + l * Hh);
        k_node_update<<<NB_N, NT, SM_SMALL>>>(Wc + (size_t)l * Hh * Hh, bcp + l * Hh,
                                              Wn1 + (size_t)l * 256 * Hh, bn1 + l * Hh,
                                              Wn2 + (size_t)l * Hh * Hh, bn2 + l * Hh,
                                              lng + l * Hh, lnb + l * Hh);
    }
    k_decode<<<NB_N, NT, SM_C>>>(Wd1, bd1, Wd2, bd2, out);
}

// round 17
// speedup vs baseline: 1.0327x; 1.0327x over previous
#include <cuda_runtime.h>
#include <math.h>
#include <stdint.h>

#define Nn 50000
#define EE 500000
#define Hh 128
#define Ll 6
#define BM 64
#define NT 256
#define H4 32

#define SA 68    // u32 stride of packed A rows
#define SW 136   // u32 stride of packed W (k-pair rows)
#define SC 132   // float stride of C buffer

#define WHALF (64 * SW)  // 8704
#define AHALF (64 * SA)  // 4352
#define CSZ (64 * SC)

#define NB_N ((Nn + BM - 1) / BM)
#define NB_E ((EE + BM - 1) / BM)
#define NSB ((Nn + 255) / 256)  // 196 scan blocks

__device__ float g_h[(size_t)Nn * Hh];
__device__ float g_ta[(size_t)Nn * Hh];
__device__ float g_tb[(size_t)Nn * Hh];
__device__ uint32_t g_eah[(size_t)EE * 64];  // edge_attr packed bf16 hi (dst-sorted order)
__device__ uint32_t g_eal[(size_t)EE * 64];  // edge_attr packed bf16 lo (dst-sorted order)
__device__ float g_agg[(size_t)Nn * Hh];
__device__ float g_deg[Nn];
__device__ int g_cnt[Nn];    // histogram -> exclusive offsets -> ranks
__device__ int g_bsum[256];  // per-scanblock sums
__device__ int g_srcs[EE];   // src node, dst-sorted edge order
__device__ int g_dsts[EE];   // dst node, dst-sorted edge order
__device__ float g_Wc[(size_t)Ll * Hh * Hh];  // We2@Wn1agg per layer
__device__ float g_bc[Ll * Hh];               // be2@Wn1agg per layer
__device__ int g_is64;

__device__ __forceinline__ float silu_f(float v) { return v / (1.0f + expf(-v)); }

__device__ __forceinline__ int ld_idx(const void* ei, long long pos, int is64) {
    if (is64) return (int)((const long long*)ei)[pos];
    return ((const int*)ei)[pos];
}

__global__ void k_detect(const int* __restrict__ ei32) {
    int v = ei32[2 * threadIdx.x + 1];
    unsigned m = __ballot_sync(0xffffffffu, v != 0);
    if (threadIdx.x == 0) g_is64 = (m == 0u) ? 1 : 0;
}

// ---- counting sort of edges by dst (hierarchical scan) ---------------------

__global__ void k_hist(const void* __restrict__ ei) {
    long long e = (long long)blockIdx.x * 256 + threadIdx.x;
    if (e < EE) {
        int d = ld_idx(ei, (long long)EE + e, g_is64);
        atomicAdd(&g_cnt[d], 1);
    }
}

__global__ void k_scan1() {  // also materializes g_deg from the histogram
    int i = blockIdx.x * 256 + threadIdx.x;
    int c0 = (i < Nn) ? g_cnt[i] : 0;
    if (i < Nn) g_deg[i] = (float)c0;
    int v = c0;
#pragma unroll
    for (int o = 16; o; o >>= 1) v += __shfl_down_sync(0xffffffffu, v, o);
    __shared__ int ws[8];
    if ((threadIdx.x & 31) == 0) ws[threadIdx.x >> 5] = v;
    __syncthreads();
    if (threadIdx.x < 8) {
        int s = ws[threadIdx.x];
#pragma unroll
        for (int o = 4; o; o >>= 1) s += __shfl_down_sync(0xffu, s, o);
        if (threadIdx.x == 0) g_bsum[blockIdx.x] = s;
    }
}

__global__ void k_scan2() {  // 1 block, 256 threads
    __shared__ int sm[256];
    int t = threadIdx.x;
    int v = (t < NSB) ? g_bsum[t] : 0;
    sm[t] = v;
    __syncthreads();
    for (int o = 1; o < 256; o <<= 1) {
        int u = (t >= o) ? sm[t - o] : 0;
        __syncthreads();
        sm[t] += u;
        __syncthreads();
    }
    if (t < NSB) g_bsum[t] = sm[t] - v;  // exclusive
}

__global__ void k_scan3() {
    int i = blockIdx.x * 256 + threadIdx.x;
    int t = threadIdx.x;
    int v = (i < Nn) ? g_cnt[i] : 0;
    __shared__ int sm[256];
    sm[t] = v;
    __syncthreads();
    for (int o = 1; o < 256; o <<= 1) {
        int u = (t >= o) ? sm[t - o] : 0;
        __syncthreads();
        sm[t] += u;
        __syncthreads();
    }
    if (i < Nn) g_cnt[i] = g_bsum[blockIdx.x] + sm[t] - v;
}

__global__ void k_scat(const void* __restrict__ ei) {
    long long e = (long long)blockIdx.x * 256 + threadIdx.x;
    if (e < EE) {
        int s = ld_idx(ei, e, g_is64);
        int d = ld_idx(ei, (long long)EE + e, g_is64);
        int pos = atomicAdd(&g_cnt[d], 1);
        g_srcs[pos] = s;
        g_dsts[pos] = d;
    }
}

// ---- weight fusion: Wc = We2@Wn1agg, bc = be2@Wn1agg (per layer) ----------

__global__ void k_fuse(const float* __restrict__ We2, const float* __restrict__ be2,
                       const float* __restrict__ Wn1) {
    extern __shared__ float fsm[];  // [0,16384): Wagg, [16384,32768): We
    float* sW = fsm;
    float* sWe = fsm + 16384;
    int l = blockIdx.x;
    const float* Wagg = Wn1 + (size_t)l * 256 * Hh + 128 * Hh;
    const float* We = We2 + (size_t)l * Hh * Hh;
    const float* be = be2 + l * Hh;
    int tid = threadIdx.x;
    for (int i = tid; i < Hh * Hh; i += 256) sW[i] = Wagg[i];
    for (int i = tid; i < Hh * Hh; i += 256) sWe[i] = We[i];
    __syncthreads();
    for (int out = tid; out < Hh * Hh; out += 256) {
        int k = out >> 7, n = out & 127;
        float s = 0.f;
#pragma unroll 8
        for (int j = 0; j < Hh; j++) s = fmaf(sWe[k * Hh + j], sW[j * Hh + n], s);
        g_Wc[(size_t)l * Hh * Hh + out] = s;
    }
    if (tid < Hh) {
        float s = 0.f;
        for (int j = 0; j < Hh; j++) s = fmaf(be[j], sW[j * Hh + tid], s);
        g_bc[l * Hh + tid] = s;
    }
}

// ---- bf16 split helpers --------------------------------------------------

__device__ __forceinline__ uint32_t pack_bf16(float lo, float hi) {
    uint32_t r;
    asm("cvt.rn.bf16x2.f32 %0, %1, %2;" : "=r"(r) : "f"(hi), "f"(lo));
    return r;
}

__device__ __forceinline__ void split2(float x, float y, uint32_t& hp, uint32_t& lp) {
    hp = pack_bf16(x, y);
    float hx = __uint_as_float(hp << 16);
    float hy = __uint_as_float(hp & 0xffff0000u);
    lp = pack_bf16(x - hx, y - hy);
}

__device__ __forceinline__ uint32_t s2u(const void* p) {
    return (uint32_t)__cvta_generic_to_shared(p);
}

// ---- W conversion --------------------------------------------------------

template <int NTHR>
__device__ __forceinline__ void conv_W(const float* __restrict__ W, uint32_t* Wh, uint32_t* Wl,
                                       int tid) {
#pragma unroll
    for (int i = 0; i < 2048 / NTHR; i++) {
        int t = tid + i * NTHR;  // 2048 tasks: 64 k2-rows x 32 n-quads
        int k2 = t >> 5, nq = t & 31;
        float4 r0 = ((const float4*)W)[(2 * k2) * 32 + nq];
        float4 r1 = ((const float4*)W)[(2 * k2 + 1) * 32 + nq];
        uint32_t* ph = Wh + k2 * SW + nq * 4;
        uint32_t* pl = Wl + k2 * SW + nq * 4;
        uint32_t h, l;
        split2(r0.x, r1.x, h, l); ph[0] = h; pl[0] = l;
        split2(r0.y, r1.y, h, l); ph[1] = h; pl[1] = l;
        split2(r0.z, r1.z, h, l); ph[2] = h; pl[2] = l;
        split2(r0.w, r1.w, h, l); ph[3] = h; pl[3] = l;
    }
}

// ---- A conversion --------------------------------------------------------

template <int ROWS, int NTHR>
__device__ __forceinline__ void conv_A(const float* __restrict__ g, long long r0, long long rmax,
                                       uint32_t* Ah, uint32_t* Al, int tid) {
#pragma unroll
    for (int i = 0; i < ROWS * 32 / NTHR; i++) {
        int idx = tid + i * NTHR;
        int m = idx >> 5, q = idx & 31;
        float4 v = make_float4(0.f, 0.f, 0.f, 0.f);
        if (r0 + m < rmax) v = ((const float4*)g)[(r0 + m) * (long long)H4 + q];
        uint32_t h, l;
        split2(v.x, v.y, h, l);
        Ah[m * SA + q * 2] = h; Al[m * SA + q * 2] = l;
        split2(v.z, v.w, h, l);
        Ah[m * SA + q * 2 + 1] = h; Al[m * SA + q * 2 + 1] = l;
    }
}

// Async copy pre-packed edge_attr (sorted order, sequential) into smem A tiles.
__device__ __forceinline__ void prefetch_ea(long long e0, uint32_t* Ah, uint32_t* Al, int tid) {
#pragma unroll
    for (int i = 0; i < 8; i++) {
        int idx = tid + i * NT;
        int m = idx >> 5, q = idx & 31;
        long long e = e0 + m;
        uint32_t ssz = (e < EE) ? 8u : 0u;
        long long ec = (e < EE) ? e : 0;
        const void* gh = (const void*)(g_eah + ec * 64 + q * 2);
        const void* gl = (const void*)(g_eal + ec * 64 + q * 2);
        uint32_t sh = s2u(&Ah[m * SA + q * 2]);
        uint32_t sl = s2u(&Al[m * SA + q * 2]);
        asm volatile("cp.async.ca.shared.global [%0], [%1], 8, %2;" ::"r"(sh), "l"(gh), "r"(ssz));
        asm volatile("cp.async.ca.shared.global [%0], [%1], 8, %2;" ::"r"(sl), "l"(gl), "r"(ssz));
    }
    asm volatile("cp.async.commit_group;" ::: "memory");
}

__device__ __forceinline__ void conv_A_scaled(const float* __restrict__ g, long long r0,
                                              long long rmax, uint32_t* Ah, uint32_t* Al, int tid,
                                              const float* __restrict__ rden) {
#pragma unroll
    for (int i = 0; i < 8; i++) {
        int idx = tid + i * NT;
        int m = idx >> 5, q = idx & 31;
        float4 v = make_float4(0.f, 0.f, 0.f, 0.f);
        if (r0 + m < rmax) {
            v = ((const float4*)g)[(r0 + m) * (long long)H4 + q];
            float s = rden[m];
            v.x *= s; v.y *= s; v.z *= s; v.w *= s;
        }
        uint32_t h, l;
        split2(v.x, v.y, h, l);
        Ah[m * SA + q * 2] = h; Al[m * SA + q * 2] = l;
        split2(v.z, v.w, h, l);
        Ah[m * SA + q * 2 + 1] = h; Al[m * SA + q * 2 + 1] = l;
    }
}

// ---- mma ------------------------------------------------------------------

__device__ __forceinline__ void mma_b(float c[4], uint32_t a0, uint32_t a1, uint32_t a2,
                                      uint32_t a3, uint32_t b0, uint32_t b1) {
    asm volatile(
        "mma.sync.aligned.m16n8k16.row.col.f32.bf16.bf16.f32 "
        "{%0,%1,%2,%3},{%4,%5,%6,%7},{%8,%9},{%0,%1,%2,%3};"
        : "+f"(c[0]), "+f"(c[1]), "+f"(c[2]), "+f"(c[3])
        : "r"(a0), "r"(a1), "r"(a2), "r"(a3), "r"(b0), "r"(b1));
}

__device__ __forceinline__ void zero_acc(float acc[2][4][4]) {
#pragma unroll
    for (int mt = 0; mt < 2; mt++)
#pragma unroll
        for (int nt = 0; nt < 4; nt++)
#pragma unroll
            for (int j = 0; j < 4; j++) acc[mt][nt][j] = 0.f;
}

// warp tile 32x32 at (wm*32, wn*32); 3-term bf16 split.
__device__ __forceinline__ void mma_gemm(const uint32_t* __restrict__ Ah,
                                         const uint32_t* __restrict__ Al,
                                         const uint32_t* __restrict__ Wh,
                                         const uint32_t* __restrict__ Wl, float acc[2][4][4],
                                         int lane, int wm, int wn) {
    int g = lane >> 2, tg = lane & 3;
#pragma unroll 1
    for (int kc = 0; kc < 8; kc++) {
        uint32_t ah[2][4], al[2][4], bh[4][2], bl[4][2];
#pragma unroll
        for (int mt = 0; mt < 2; mt++) {
            const uint32_t* p = Ah + (wm * 32 + mt * 16 + g) * SA + kc * 8;
            const uint32_t* q = Al + (wm * 32 + mt * 16 + g) * SA + kc * 8;
            ah[mt][0] = p[tg]; ah[mt][1] = p[8 * SA + tg];
            ah[mt][2] = p[tg + 4]; ah[mt][3] = p[8 * SA + tg + 4];
            al[mt][0] = q[tg]; al[mt][1] = q[8 * SA + tg];
            al[mt][2] = q[tg + 4]; al[mt][3] = q[8 * SA + tg + 4];
        }
#pragma unroll
        for (int nt = 0; nt < 4; nt++) {
            const uint32_t* p = Wh + (kc * 8 + tg) * SW + wn * 32 + nt * 8 + g;
            const uint32_t* q = Wl + (kc * 8 + tg) * SW + wn * 32 + nt * 8 + g;
            bh[nt][0] = p[0]; bh[nt][1] = p[4 * SW];
            bl[nt][0] = q[0]; bl[nt][1] = q[4 * SW];
        }
#pragma unroll
        for (int mt = 0; mt < 2; mt++)
#pragma unroll
            for (int nt = 0; nt < 4; nt++) {
                mma_b(acc[mt][nt], ah[mt][0], ah[mt][1], ah[mt][2], ah[mt][3], bh[nt][0], bh[nt][1]);
                mma_b(acc[mt][nt], ah[mt][0], ah[mt][1], ah[mt][2], ah[mt][3], bl[nt][0], bl[nt][1]);
                mma_b(acc[mt][nt], al[mt][0], al[mt][1], al[mt][2], al[mt][3], bh[nt][0], bh[nt][1]);
            }
    }
}

__device__ __forceinline__ void store_C(const float acc[2][4][4], float* C, int lane, int wm,
                                        int wn) {
    int g = lane >> 2, tg = lane & 3;
#pragma unroll
    for (int mt = 0; mt < 2; mt++)
#pragma unroll
        for (int nt = 0; nt < 4; nt++) {
            int r = wm * 32 + mt * 16 + g;
            int c = wn * 32 + nt * 8 + 2 * tg;
            *(float2*)(C + r * SC + c) = make_float2(acc[mt][nt][0], acc[mt][nt][1]);
            *(float2*)(C + (r + 8) * SC + c) = make_float2(acc[mt][nt][2], acc[mt][nt][3]);
        }
}

__device__ __forceinline__ void out_direct(const float acc[2][4][4], float* __restrict__ out,
                                           long long r0, long long rmax, int lane, int wm, int wn,
                                           const float* bias) {
    int g = lane >> 2, tg = lane & 3;
#pragma unroll
    for (int mt = 0; mt < 2; mt++)
#pragma unroll
        for (int nt = 0; nt < 4; nt++) {
            int r = wm * 32 + mt * 16 + g;
            int c = wn * 32 + nt * 8 + 2 * tg;
            float bx = 0.f, by = 0.f;
            if (bias) { bx = bias[c]; by = bias[c + 1]; }
            if (r0 + r < rmax)
                *(float2*)(out + (r0 + r) * (long long)Hh + c) =
                    make_float2(acc[mt][nt][0] + bx, acc[mt][nt][1] + by);
            if (r0 + r + 8 < rmax)
                *(float2*)(out + (r0 + r + 8) * (long long)Hh + c) =
                    make_float2(acc[mt][nt][2] + bx, acc[mt][nt][3] + by);
        }
}

// ---- node encoder (2 CTAs/SM) ---------------------------------------------

__global__ __launch_bounds__(NT, 2) void k_node_encode(const float* __restrict__ x,
                                                       const float* __restrict__ W1,
                                                       const float* __restrict__ b1,
                                                       const float* __restrict__ W2,
                                                       const float* __restrict__ b2) {
    extern __shared__ __align__(16) uint32_t dsm[];
    uint32_t* Wh = dsm;
    uint32_t* Wl = Wh + WHALF;
    uint32_t* Ah = Wl + WHALF;
    uint32_t* Al = Ah + AHALF;
    __shared__ float xt[BM][3];
    __shared__ __align__(16) float W1s[3 * Hh];
    __shared__ __align__(16) float b1s[Hh];
    __shared__ __align__(16) float b2s[Hh];
    int tid = threadIdx.x, lane = tid & 31, w = tid >> 5, wm = w & 1, wn = w >> 1;
    int tx = tid & 31, ty = tid >> 5;
    long long r0 = (long long)blockIdx.x * BM;

    if (tid < BM) {
        long long m = r0 + tid;
        float a = 0.f, bb = 0.f, c = 0.f;
        if (m < Nn) { a = x[m * 3 + 0]; bb = x[m * 3 + 1]; c = x[m * 3 + 2]; }
        xt[tid][0] = a; xt[tid][1] = bb; xt[tid][2] = c;
    }
    if (tid < Hh) { b1s[tid] = b1[tid]; b2s[tid] = b2[tid]; }
    for (int i = tid; i < 3 * Hh; i += NT) W1s[i] = W1[i];
    conv_W<NT>(W2, Wh, Wl, tid);
    __syncthreads();

    int row0 = ty * 8, col0 = tx * 4;
#pragma unroll
    for (int i = 0; i < 8; i++) {
        int r = row0 + i;
        float v[4];
#pragma unroll
        for (int j = 0; j < 4; j++) {
            int c = col0 + j;
            v[j] = silu_f(b1s[c] + xt[r][0] * W1s[c] + xt[r][1] * W1s[Hh + c] +
                          xt[r][2] * W1s[2 * Hh + c]);
        }
        uint32_t h, l;
        split2(v[0], v[1], h, l);
        Ah[r * SA + tx * 2] = h; Al[r * SA + tx * 2] = l;
        split2(v[2], v[3], h, l);
        Ah[r * SA + tx * 2 + 1] = h; Al[r * SA + tx * 2 + 1] = l;
    }
    __syncthreads();

    float acc[2][4][4];
    zero_acc(acc);
    mma_gemm(Ah, Al, Wh, Wl, acc, lane, wm, wn);
    out_direct(acc, g_h, r0, Nn, lane, wm, wn, b2s);
}

// ---- edge encoder (persistent, dst-sorted order, 2 CTAs/SM) ----------------
// Writes edge_attr packed at sorted position; output staged through smem
// so the global stores are coalesced uint2 rows.

__global__ __launch_bounds__(NT, 2) void k_edge_encode(const float* __restrict__ coords,
                                                       const float* __restrict__ W1,
                                                       const float* __restrict__ b1,
                                                       const float* __restrict__ W2,
                                                       const float* __restrict__ b2) {
    extern __shared__ __align__(16) uint32_t dsm[];
    uint32_t* Wh = dsm;
    uint32_t* Wl = Wh + WHALF;
    uint32_t* Ah = Wl + WHALF;
    uint32_t* Al = Ah + AHALF;
    __shared__ float ef[BM][4];
    __shared__ __align__(16) float W1s[4 * Hh];
    __shared__ __align__(16) float b1s[Hh];
    __shared__ __align__(16) float b2s[Hh];
    int tid = threadIdx.x, lane = tid & 31, w = tid >> 5, wm = w & 1, wn = w >> 1;
    int tx = tid & 31, ty = tid >> 5;
    int g = lane >> 2, tg = lane & 3;

    if (tid < Hh) { b1s[tid] = b1[tid]; b2s[tid] = b2[tid]; }
    for (int i = tid; i < 4 * Hh; i += NT) W1s[i] = W1[i];
    conv_W<NT>(W2, Wh, Wl, tid);
    __syncthreads();

    for (long long tile = blockIdx.x; tile < NB_E; tile += gridDim.x) {
        long long e0 = tile * BM;
        if (tid < BM) {
            long long e = e0 + tid;
            float dx = 0.f, dy = 0.f, dz = 0.f, nr = 0.f;
            if (e < EE) {
                int s = g_srcs[e];
                int d = g_dsts[e];
                dx = coords[(size_t)d * 3 + 0] - coords[(size_t)s * 3 + 0];
                dy = coords[(size_t)d * 3 + 1] - coords[(size_t)s * 3 + 1];
                dz = coords[(size_t)d * 3 + 2] - coords[(size_t)s * 3 + 2];
                nr = sqrtf(dx * dx + dy * dy + dz * dz);
            }
            ef[tid][0] = dx; ef[tid][1] = dy; ef[tid][2] = dz; ef[tid][3] = nr;
        }
        __syncthreads();

        int row0 = ty * 8, col0 = tx * 4;
#pragma unroll
        for (int i = 0; i < 8; i++) {
            int r = row0 + i;
            float v[4];
#pragma unroll
            for (int j = 0; j < 4; j++) {
                int c = col0 + j;
                v[j] = silu_f(b1s[c] + ef[r][0] * W1s[c] + ef[r][1] * W1s[Hh + c] +
                              ef[r][2] * W1s[2 * Hh + c] + ef[r][3] * W1s[3 * Hh + c]);
            }
            uint32_t h, l;
            split2(v[0], v[1], h, l);
            Ah[r * SA + tx * 2] = h; Al[r * SA + tx * 2] = l;
            split2(v[2], v[3], h, l);
            Ah[r * SA + tx * 2 + 1] = h; Al[r * SA + tx * 2 + 1] = l;
        }
        __syncthreads();

        float acc[2][4][4];
        zero_acc(acc);
        mma_gemm(Ah, Al, Wh, Wl, acc, lane, wm, wn);
        __syncthreads();  // all A reads done; Ah/Al reusable as output staging

        // stage packed (acc + b2) into Ah/Al at acc-layout positions
#pragma unroll
        for (int mt = 0; mt < 2; mt++)
#pragma unroll
            for (int nt = 0; nt < 4; nt++) {
                int r = wm * 32 + mt * 16 + g;
                int c = wn * 32 + nt * 8 + 2 * tg;
                int k2 = c >> 1;
                float bx = b2s[c], by = b2s[c + 1];
                uint32_t h, l;
                split2(acc[mt][nt][0] + bx, acc[mt][nt][1] + by, h, l);
                Ah[r * SA + k2] = h;
                Al[r * SA + k2] = l;
                split2(acc[mt][nt][2] + bx, acc[mt][nt][3] + by, h, l);
                Ah[(r + 8) * SA + k2] = h;
                Al[(r + 8) * SA + k2] = l;
            }
        __syncthreads();

        // coalesced store out
#pragma unroll
        for (int i = 0; i < 8; i++) {
            int idx = tid + i * NT;
            int m = idx >> 5, q = idx & 31;
            if (e0 + m < EE) {
                ((uint2*)(g_eah + (e0 + m) * 64))[q] = *(uint2*)&Ah[m * SA + q * 2];
                ((uint2*)(g_eal + (e0 + m) * 64))[q] = *(uint2*)&Al[m * SA + q * 2];
            }
        }
        __syncthreads();
    }
}

// ---- per layer: ta/tb (persistent, parity-split, 2 CTAs/SM) ----------------

__global__ __launch_bounds__(NT, 2) void k_tatb(const float* __restrict__ W1) {
    extern __shared__ __align__(16) uint32_t dsm[];
    uint32_t* Wh = dsm;
    uint32_t* Wl = Wh + WHALF;
    uint32_t* Ah = Wl + WHALF;
    uint32_t* Al = Ah + AHALF;
    int tid = threadIdx.x, lane = tid & 31, w = tid >> 5, wm = w & 1, wn = w >> 1;
    int part = blockIdx.x & 1;  // 0 -> W1a/g_ta, 1 -> W1b/g_tb

    conv_W<NT>(W1 + part * Hh * Hh, Wh, Wl, tid);
    __syncthreads();
    float* outp = part ? g_tb : g_ta;

    for (long long tile = blockIdx.x >> 1; tile < NB_N; tile += gridDim.x >> 1) {
        long long r0 = tile * BM;
        conv_A<BM, NT>(g_h, r0, Nn, Ah, Al, tid);
        __syncthreads();
        float acc[2][4][4];
        zero_acc(acc);
        mma_gemm(Ah, Al, Wh, Wl, acc, lane, wm, wn);
        out_direct(acc, outp, r0, Nn, lane, wm, wn, 0);
        __syncthreads();
    }
}

// ---- per layer: fused edge kernel (persistent, dst-sorted, cp.async) ------
// hid = silu(ea@W1c + b1 + ta[dst] + tb[src]); scatter hid to g_agg[dst].

__global__ __launch_bounds__(NT, 2) void k_edge(const float* __restrict__ W1,
                                                const float* __restrict__ b1) {
    extern __shared__ __align__(16) uint32_t dsm[];
    uint32_t* W1h = dsm;
    uint32_t* W1l = W1h + WHALF;
    uint32_t* Ah = W1l + WHALF;
    uint32_t* Al = Ah + AHALF;
    __shared__ int dsts[2][BM];
    __shared__ int srcs[2][BM];
    __shared__ __align__(16) float b1s[Hh];
    int tid = threadIdx.x, lane = tid & 31, w = tid >> 5, wm = w & 1, wn = w >> 1;
    int g = lane >> 2, tg = lane & 3;

    if (tid < Hh) b1s[tid] = b1[tid];
    conv_W<NT>(W1 + 256 * Hh, W1h, W1l, tid);  // W1c rows [256,384)

    long long tile = blockIdx.x;
    int buf = 0;
    prefetch_ea(tile * BM, Ah, Al, tid);
    if (tid < BM) {
        long long e = tile * BM + tid;
        int s = 0, d = 0;
        if (e < EE) { s = g_srcs[e]; d = g_dsts[e]; }
        srcs[0][tid] = s;
        dsts[0][tid] = d;
    }

    for (; tile < NB_E; tile += gridDim.x) {
        long long e0 = tile * BM;
        asm volatile("cp.async.wait_group 0;" ::: "memory");
        __syncthreads();  // A + idx[buf] + W ready

        float acc[2][4][4];
        zero_acc(acc);
        mma_gemm(Ah, Al, W1h, W1l, acc, lane, wm, wn);
        __syncthreads();  // all A reads done; safe to overwrite

        long long next = tile + gridDim.x;
        if (next < NB_E) {
            prefetch_ea(next * BM, Ah, Al, tid);  // overlaps epilogue below
            if (tid < BM) {
                long long e = next * BM + tid;
                int s = 0, d = 0;
                if (e < EE) { s = g_srcs[e]; d = g_dsts[e]; }
                srcs[1 - buf][tid] = s;
                dsts[1 - buf][tid] = d;
            }
        }

        // epilogue: silu + gather ta/tb, scatter hid straight to g_agg[dst]
#pragma unroll
        for (int mt = 0; mt < 2; mt++)
#pragma unroll
            for (int half = 0; half < 2; half++) {
                int r = wm * 32 + mt * 16 + g + half * 8;
                long long e = e0 + r;
                if (e < EE) {
                    int dd = dsts[buf][r], ss = srcs[buf][r];
                    const float* tap = g_ta + (size_t)dd * Hh;
                    const float* tbp = g_tb + (size_t)ss * Hh;
                    float* aggp = g_agg + (size_t)dd * Hh;
#pragma unroll
                    for (int nt = 0; nt < 4; nt++) {
                        int c = wn * 32 + nt * 8 + 2 * tg;
                        float2 tav = *(const float2*)(tap + c);
                        float2 tbv = *(const float2*)(tbp + c);
                        float v0 = silu_f(acc[mt][nt][half * 2 + 0] + b1s[c] + tav.x + tbv.x);
                        float v1 = silu_f(acc[mt][nt][half * 2 + 1] + b1s[c + 1] + tav.y + tbv.y);
                        asm volatile("red.global.add.v2.f32 [%0], {%1,%2};" ::"l"(aggp + c),
                                     "f"(v0), "f"(v1)
                                     : "memory");
                    }
                }
            }
        buf ^= 1;
    }
}

// ---- per layer: node update (3 GEMMs, no C buffer, 2 CTAs/SM) --------------
// u = agg_hid/denom ; acc = u@Wc + h@Wn1h
// upd = silu(acc + bn1 + cdeg*bc)@Wn2 + bn2 ; h = LN(upd + h)

__global__ __launch_bounds__(NT, 2) void k_node_update(const float* __restrict__ Wc,
                                                       const float* __restrict__ bc,
                                                       const float* __restrict__ Wn1,
                                                       const float* __restrict__ bn1,
                                                       const float* __restrict__ Wn2,
                                                       const float* __restrict__ bn2,
                                                       const float* __restrict__ lg,
                                                       const float* __restrict__ lb) {
    extern __shared__ __align__(16) uint32_t dsm[];
    uint32_t* Wh = dsm;
    uint32_t* Wl = Wh + WHALF;
    uint32_t* Ah = Wl + WHALF;
    uint32_t* Al = Ah + AHALF;
    __shared__ float rden[BM];
    __shared__ float cdeg[BM];
    __shared__ __align__(16) float bcs[Hh];   // bc
    __shared__ __align__(16) float b1s[Hh];   // bn1
    __shared__ __align__(16) float b2s[Hh];   // bn2
    __shared__ __align__(16) float gs[Hh];
    __shared__ __align__(16) float bs[Hh];
    __shared__ float red_s[BM][4];
    __shared__ float red_q[BM][4];
    int tid = threadIdx.x, lane = tid & 31, w = tid >> 5, wm = w & 1, wn = w >> 1;
    int g = lane >> 2, tg = lane & 3;
    long long r0 = (long long)blockIdx.x * BM;

    if (tid < BM) {
        long long m = r0 + tid;
        float dg = (m < Nn) ? g_deg[m] : 0.f;
        rden[tid] = 1.0f / fmaxf(dg, 1.0f);
        cdeg[tid] = (dg > 0.f) ? 1.f : 0.f;
    }
    if (tid < Hh) {
        bcs[tid] = bc[tid];
        b1s[tid] = bn1[tid];
        b2s[tid] = bn2[tid];
        gs[tid] = lg[tid];
        bs[tid] = lb[tid];
    }
    __syncthreads();  // rden/cdeg visible before conv_A_scaled

    // 1) u = agg/denom ; Wc
    conv_A_scaled(g_agg, r0, Nn, Ah, Al, tid, rden);
    conv_W<NT>(Wc, Wh, Wl, tid);
    __syncthreads();

    // 2) acc = u@Wc
    float acc[2][4][4];
    zero_acc(acc);
    mma_gemm(Ah, Al, Wh, Wl, acc, lane, wm, wn);
    __syncthreads();

    // 3) h part: acc += h@Wn1h
    conv_A<BM, NT>(g_h, r0, Nn, Ah, Al, tid);
    conv_W<NT>(Wn1, Wh, Wl, tid);  // Wn1 h part (rows [0,128))
    __syncthreads();
    mma_gemm(Ah, Al, Wh, Wl, acc, lane, wm, wn);
    __syncthreads();  // all reads of Ah/Al + Wh/Wl done before overwrite

    // 4) silu(acc + bn1 + cdeg*bc) -> packed A (acc layout) ; Wn2
#pragma unroll
    for (int mt = 0; mt < 2; mt++)
#pragma unroll
        for (int half = 0; half < 2; half++) {
            int r = wm * 32 + mt * 16 + g + half * 8;
            float cf = cdeg[r];
#pragma unroll
            for (int nt = 0; nt < 4; nt++) {
                int c = wn * 32 + nt * 8 + 2 * tg;
                float v0 = silu_f(acc[mt][nt][half * 2 + 0] + b1s[c] + cf * bcs[c]);
                float v1 = silu_f(acc[mt][nt][half * 2 + 1] + b1s[c + 1] + cf * bcs[c + 1]);
                uint32_t h, l;
                split2(v0, v1, h, l);
                int k2 = wn * 16 + nt * 4 + tg;
                Ah[r * SA + k2] = h;
                Al[r * SA + k2] = l;
            }
        }
    conv_W<NT>(Wn2, Wh, Wl, tid);
    __syncthreads();

    // 5) acc = hidden@Wn2
    zero_acc(acc);
    mma_gemm(Ah, Al, Wh, Wl, acc, lane, wm, wn);

    // 6) residual + layernorm, all in acc layout
#pragma unroll
    for (int mt = 0; mt < 2; mt++)
#pragma unroll
        for (int half = 0; half < 2; half++) {
            int r = wm * 32 + mt * 16 + g + half * 8;
            long long m = r0 + r;
            float s = 0.f, q = 0.f;
#pragma unroll
            for (int nt = 0; nt < 4; nt++) {
                int c = wn * 32 + nt * 8 + 2 * tg;
                float2 hv = make_float2(0.f, 0.f);
                if (m < Nn) hv = *(const float2*)(g_h + m * (long long)Hh + c);
                float v0 = acc[mt][nt][half * 2 + 0] + b2s[c] + hv.x;
                float v1 = acc[mt][nt][half * 2 + 1] + b2s[c + 1] + hv.y;
                acc[mt][nt][half * 2 + 0] = v0;
                acc[mt][nt][half * 2 + 1] = v1;
                s += v0 + v1;
                q += v0 * v0 + v1 * v1;
            }
            s += __shfl_xor_sync(0xffffffffu, s, 1);
            q += __shfl_xor_sync(0xffffffffu, q, 1);
            s += __shfl_xor_sync(0xffffffffu, s, 2);
            q += __shfl_xor_sync(0xffffffffu, q, 2);
            if (tg == 0) { red_s[r][wn] = s; red_q[r][wn] = q; }
        }
    __syncthreads();

#pragma unroll
    for (int mt = 0; mt < 2; mt++)
#pragma unroll
        for (int half = 0; half < 2; half++) {
            int r = wm * 32 + mt * 16 + g + half * 8;
            long long m = r0 + r;
            float s = red_s[r][0] + red_s[r][1] + red_s[r][2] + red_s[r][3];
            float q = red_q[r][0] + red_q[r][1] + red_q[r][2] + red_q[r][3];
            float mean = s * (1.0f / Hh);
            float var = q * (1.0f / Hh) - mean * mean;
            float inv = 1.0f / sqrtf(var + 1e-5f);
            if (m < Nn) {
#pragma unroll
                for (int nt = 0; nt < 4; nt++) {
                    int c = wn * 32 + nt * 8 + 2 * tg;
                    float o0 = (acc[mt][nt][half * 2 + 0] - mean) * inv * gs[c] + bs[c];
                    float o1 = (acc[mt][nt][half * 2 + 1] - mean) * inv * gs[c + 1] + bs[c + 1];
                    *(float2*)(g_h + m * (long long)Hh + c) = make_float2(o0, o1);
                }
            }
        }
}

// ---- decoder --------------------------------------------------------------

__global__ __launch_bounds__(NT, 1) void k_decode(const float* __restrict__ W1,
                                                  const float* __restrict__ b1,
                                                  const float* __restrict__ W2,
                                                  const float* __restrict__ b2,
                                                  float* __restrict__ out) {
    extern __shared__ __align__(16) uint32_t dsm[];
    uint32_t* Wh = dsm;
    uint32_t* Wl = Wh + WHALF;
    uint32_t* Ah = Wl + WHALF;
    uint32_t* Al = Ah + AHALF;
    float* C = (float*)(Al + AHALF);
    __shared__ __align__(16) float b1s[Hh];
    __shared__ float W2s[Hh * 9];
    __shared__ float b2s[9];
    int tid = threadIdx.x, lane = tid & 31, w = tid >> 5, wm = w & 1, wn = w >> 1;
    int tx = tid & 31, ty = tid >> 5;
    int row0 = ty * 8, col0 = tx * 4;
    long long r0 = (long long)blockIdx.x * BM;

    if (tid < Hh) b1s[tid] = b1[tid];
    if (tid < 9) b2s[tid] = b2[tid];
    for (int i = tid; i < Hh * 9; i += NT) W2s[i] = W2[i];
    conv_A<BM, NT>(g_h, r0, Nn, Ah, Al, tid);
    conv_W<NT>(W1, Wh, Wl, tid);
    __syncthreads();

    float acc[2][4][4];
    zero_acc(acc);
    mma_gemm(Ah, Al, Wh, Wl, acc, lane, wm, wn);
    __syncthreads();
    store_C(acc, C, lane, wm, wn);
    __syncthreads();

#pragma unroll
    for (int i = 0; i < 8; i++) {
        int r = row0 + i;
        float4 cv = *(const float4*)(C + r * SC + col0);
        cv.x = silu_f(cv.x + b1s[col0 + 0]);
        cv.y = silu_f(cv.y + b1s[col0 + 1]);
        cv.z = silu_f(cv.z + b1s[col0 + 2]);
        cv.w = silu_f(cv.w + b1s[col0 + 3]);
        *(float4*)(C + r * SC + col0) = cv;
    }
    __syncthreads();

    for (int idx = tid; idx < BM * 9; idx += NT) {
        int r = idx / 9;
        int c = idx % 9;
        long long m = r0 + r;
        if (m < Nn) {
            float sum = 0.f;
            const float* hrow = C + r * SC;
#pragma unroll 4
            for (int k = 0; k < Hh; k++) sum = fmaf(hrow[k], W2s[k * 9 + c], sum);
            out[m * 9 + c] = sum + b2s[c];
        }
    }
}

// ---- host -----------------------------------------------------------------

extern "C" void kernel_launch(void* const* d_in, const int* in_sizes, int n_in, void* d_out,
                              int out_size) {
    const float* x = (const float*)d_in[0];
    const float* coords = (const float*)d_in[1];
    const void* ei = d_in[2];
    const float* Wne1 = (const float*)d_in[3];
    const float* bne1 = (const float*)d_in[4];
    const float* Wne2 = (const float*)d_in[5];
    const float* bne2 = (const float*)d_in[6];
    const float* Wee1 = (const float*)d_in[7];
    const float* bee1 = (const float*)d_in[8];
    const float* Wee2 = (const float*)d_in[9];
    const float* bee2 = (const float*)d_in[10];
    const float* We1 = (const float*)d_in[11];
    const float* be1 = (const float*)d_in[12];
    const float* We2 = (const float*)d_in[13];
    const float* be2 = (const float*)d_in[14];
    const float* Wn1 = (const float*)d_in[15];
    const float* bn1 = (const float*)d_in[16];
    const float* Wn2 = (const float*)d_in[17];
    const float* bn2 = (const float*)d_in[18];
    const float* lng = (const float*)d_in[19];
    const float* lnb = (const float*)d_in[20];
    const float* Wd1 = (const float*)d_in[21];
    const float* bd1 = (const float*)d_in[22];
    const float* Wd2 = (const float*)d_in[23];
    const float* bd2 = (const float*)d_in[24];
    float* out = (float*)d_out;

    const int SM_SMALL = (2 * WHALF + 2 * AHALF) * 4;        // 104448 (2 CTAs/SM)
    const int SM_C = (2 * WHALF + 2 * AHALF) * 4 + CSZ * 4;  // 138240 (decode)
    const int SM_FUSE = 131072;

    cudaFuncSetAttribute(k_node_encode, cudaFuncAttributeMaxDynamicSharedMemorySize, SM_SMALL);
    cudaFuncSetAttribute(k_edge_encode, cudaFuncAttributeMaxDynamicSharedMemorySize, SM_SMALL);
    cudaFuncSetAttribute(k_tatb, cudaFuncAttributeMaxDynamicSharedMemorySize, SM_SMALL);
    cudaFuncSetAttribute(k_edge, cudaFuncAttributeMaxDynamicSharedMemorySize, SM_SMALL);
    cudaFuncSetAttribute(k_node_update, cudaFuncAttributeMaxDynamicSharedMemorySize, SM_SMALL);
    cudaFuncSetAttribute(k_decode, cudaFuncAttributeMaxDynamicSharedMemorySize, SM_C);
    cudaFuncSetAttribute(k_fuse, cudaFuncAttributeMaxDynamicSharedMemorySize, SM_FUSE);

    int dev = 0, sms = 148;
    cudaGetDevice(&dev);
    cudaDeviceGetAttribute(&sms, cudaDevAttrMultiProcessorCount, dev);

    void* p_agg = 0;
    void* p_cnt = 0;
    cudaGetSymbolAddress(&p_agg, g_agg);
    cudaGetSymbolAddress(&p_cnt, g_cnt);

    void* p_Wc = 0;
    void* p_bc = 0;
    cudaGetSymbolAddress(&p_Wc, g_Wc);
    cudaGetSymbolAddress(&p_bc, g_bc);
    const float* Wc = (const float*)p_Wc;
    const float* bcp = (const float*)p_bc;

    k_detect<<<1, 32>>>((const int*)ei);
    cudaMemsetAsync(p_cnt, 0, Nn * sizeof(int));
    k_hist<<<(EE + 255) / 256, 256>>>(ei);
    k_scan1<<<NSB, 256>>>();
    k_scan2<<<1, 256>>>();
    k_scan3<<<NSB, 256>>>();
    k_scat<<<(EE + 255) / 256, 256>>>(ei);
    k_fuse<<<Ll, 256, SM_FUSE>>>(We2, be2, Wn1);
    k_node_encode<<<NB_N, NT, SM_SMALL>>>(x, Wne1, bne1, Wne2, bne2);
    k_edge_encode<<<2 * sms, NT, SM_SMALL>>>(coords, Wee1, bee1, Wee2, bee2);

    for (int l = 0; l < Ll; l++) {
        cudaMemsetAsync(p_agg, 0, (size_t)Nn * Hh * sizeof(float));
        k_tatb<<<2 * sms, NT, SM_SMALL>>>(We1 + (size_t)l * 384 * Hh);
        k_edge<<<2 * sms, NT, SM_SMALL>>>(We1 + (size_t)l * 384 * Hh, be1 + l * Hh);
        k_node_update<<<NB_N, NT, SM_SMALL>>>(Wc + (size_t)l * Hh * Hh, bcp + l * Hh,
                                              Wn1 + (size_t)l * 256 * Hh, bn1 + l * Hh,
                                              Wn2 + (size_t)l * Hh * Hh, bn2 + l * Hh,
                                              lng + l * Hh, lnb + l * Hh);
    }
    k_decode<<<NB_N, NT, SM_C>>>(Wd1, bd1, Wd2, bd2, out);
}